// round 15
// baseline (speedup 1.0000x reference)
#include <cuda_runtime.h>
#include <cuda_fp16.h>
#include <cstdint>

// ---------------------------------------------------------------------------
// Problem: B=128, F=1024, W=32, H=64.  softmax over a size-1 axis == 1, so the
// attention branch is dead; model = plain LSTM, output = CELL state per step.
//   G[m][n] = sum_k x[b][k][t] * Wx[k][n] + b_lstm[n],  m = b*32 + t
// GEMM: fp16 mma.sync, 2-pass hi/lo compensation on A, B plain RN fp16
// (rel_err ~2.8e-4 measured, 3.5x under the 1e-3 gate).
// ---------------------------------------------------------------------------
#define B_   128
#define F_   1024
#define W_   32
#define H_   64
#define G4   256
#define M_   4096                // B_*W_
#define PADK 40                  // B smem row stride (fp16)
#define PADM 136                 // A smem row stride (fp16): 272B, ldsm-safe

__device__ float   g_G [M_ * G4];        // gate preactivations, 4 MB
__device__ __half  g_xh[F_ * M_];        // x hi  [k][m], 8 MB
__device__ __half  g_xl[F_ * M_];        // x lo  [k][m]
__device__ __half  g_wf[G4 * F_];        // Wx^T fp16 RN [n][k], 512 KB

// ---- helpers ---------------------------------------------------------------
__device__ __forceinline__ uint32_t smaddr(const void* p) {
    return (uint32_t)__cvta_generic_to_shared(p);
}
__device__ __forceinline__ void split2h(float a, float b, uint32_t& hi, uint32_t& lo) {
    __half2 h = __floats2half2_rn(a, b);
    float ra = a - __half2float(__low2half(h));
    float rb = b - __half2float(__high2half(h));
    __half2 l = __floats2half2_rn(ra, rb);
    hi = *reinterpret_cast<uint32_t*>(&h);
    lo = *reinterpret_cast<uint32_t*>(&l);
}
__device__ __forceinline__ uint32_t pack2h(float a, float b) {
    __half2 h = __floats2half2_rn(a, b);
    return *reinterpret_cast<uint32_t*>(&h);
}
__device__ __forceinline__ void mma_f16(float* c,
                                        const uint32_t* a, uint32_t b0, uint32_t b1) {
    asm volatile(
        "mma.sync.aligned.m16n8k16.row.col.f32.f16.f16.f32 "
        "{%0,%1,%2,%3}, {%4,%5,%6,%7}, {%8,%9}, {%0,%1,%2,%3};\n"
        : "+f"(c[0]), "+f"(c[1]), "+f"(c[2]), "+f"(c[3])
        : "r"(a[0]), "r"(a[1]), "r"(a[2]), "r"(a[3]), "r"(b0), "r"(b1));
}
__device__ __forceinline__ void ldsm4(uint32_t* r, uint32_t addr) {
    asm volatile("ldmatrix.sync.aligned.m8n8.x4.shared.b16 {%0,%1,%2,%3}, [%4];"
                 : "=r"(r[0]), "=r"(r[1]), "=r"(r[2]), "=r"(r[3]) : "r"(addr));
}
__device__ __forceinline__ void ldsm4t(uint32_t* r, uint32_t addr) {
    asm volatile("ldmatrix.sync.aligned.m8n8.x4.trans.shared.b16 {%0,%1,%2,%3}, [%4];"
                 : "=r"(r[0]), "=r"(r[1]), "=r"(r[2]), "=r"(r[3]) : "r"(addr));
}

// ---------------------------------------------------------------------------
// Kernel 0 (fused): fp16 conversion.
//   blocks [0, 1024):    x [B][F][W] -> g_xh/g_xl [k=f][m=b*32+t]  (hi/lo,
//                        NO transpose; 8 t per thread -> 16B stores)
//   blocks [1024, 1088): Wx [K][N]   -> g_wf [n][k]  (RN only; smem transpose)
// ---------------------------------------------------------------------------
__global__ __launch_bounds__(256) void split_xw(const float* __restrict__ x,
                                                const float* __restrict__ Wx) {
    const int tid = threadIdx.x;
    const int bid = blockIdx.x;

    if (bid < 1024) {
        const int gtid = bid * 256 + tid;
#pragma unroll
        for (int j = 0; j < 2; j++) {
            int idx = j * 262144 + gtid;        // over (f, b, th): 4*128*1024
            int th  = idx & 3;                  // group of 8 t
            int rem = idx >> 2;
            int b   = rem & 127;
            int f   = rem >> 7;                 // 0..1023
            const float* src = x + ((size_t)b * F_ + f) * W_ + th * 8;
            float4 v0 = *reinterpret_cast<const float4*>(src);
            float4 v1 = *reinterpret_cast<const float4*>(src + 4);
            uint32_t h0, l0, h1, l1, h2, l2, h3, l3;
            split2h(v0.x, v0.y, h0, l0);
            split2h(v0.z, v0.w, h1, l1);
            split2h(v1.x, v1.y, h2, l2);
            split2h(v1.z, v1.w, h3, l3);
            size_t dst = (size_t)f * M_ + b * 32 + th * 8;
            *reinterpret_cast<uint4*>(g_xh + dst) = make_uint4(h0, h1, h2, h3);
            *reinterpret_cast<uint4*>(g_xl + dst) = make_uint4(l0, l1, l2, l3);
        }
    } else {
        __shared__ float tile[64 * 65];
        const int id = bid - 1024;
        const int k0 = (id & 15) * 64;
        const int n0 = (id >> 4) * 64;
#pragma unroll
        for (int i = 0; i < 4; i++) {
            int idx = i * 256 + tid;
            int k = idx >> 4, nq = idx & 15;
            float4 v = *reinterpret_cast<const float4*>(
                Wx + (size_t)(k0 + k) * G4 + n0 + nq * 4);
            tile[k * 65 + nq * 4 + 0] = v.x; tile[k * 65 + nq * 4 + 1] = v.y;
            tile[k * 65 + nq * 4 + 2] = v.z; tile[k * 65 + nq * 4 + 3] = v.w;
        }
        __syncthreads();
        const int n  = tid >> 2;
        const int ko = (tid & 3) * 16;
        uint32_t hi[8];
#pragma unroll
        for (int p = 0; p < 8; p++)
            hi[p] = pack2h(tile[(ko + 2 * p) * 65 + n], tile[(ko + 2 * p + 1) * 65 + n]);
        size_t dst = (size_t)(n0 + n) * F_ + k0 + ko;
        *reinterpret_cast<uint4*>(g_wf + dst)     = make_uint4(hi[0], hi[1], hi[2], hi[3]);
        *reinterpret_cast<uint4*>(g_wf + dst + 8) = make_uint4(hi[4], hi[5], hi[6], hi[7]);
    }
}

// ---------------------------------------------------------------------------
// Kernel 1: fp16 mma.sync GEMM, 2-pass (Ah*B + Al*B). UNCHANGED from R13.
// ---------------------------------------------------------------------------
#define AH_E  0
#define AL_E  (32 * PADM)                            // 4352
#define B_E   (2 * 32 * PADM)                        // 8704
#define BUFE  (2 * 32 * PADM + 64 * PADK)            // 11264 elems = 22528 B
#define GEMM_SMEM (2 * BUFE * 2)                     // 45056 B

__global__ __launch_bounds__(256, 1)
void gate_gemm_mma(const float* __restrict__ bl) {
    extern __shared__ __half sm[];

    const int tid  = threadIdx.x;
    const int warp = tid >> 5;
    const int lane = tid & 31;
    const int wm   = (warp >> 2) * 64;
    const int wn   = (warp & 3) * 16;
    const int g    = lane >> 2;
    const int tq   = lane & 3;
    const int m0   = blockIdx.x * 128;
    const int n0   = blockIdx.y * 64;

    const uint32_t sb = smaddr(sm);
    const int aoff = ((lane & 7) + ((lane >> 4) & 1) * 8) * PADM
                   + ((lane >> 3) & 1) * 8 + wm;
    const uint32_t aAh = sb + 2 * (AH_E + aoff);
    const uint32_t aAl = sb + 2 * (AL_E + aoff);
    const int brow = wn + (lane & 7) + ((lane >> 4) & 1) * 8;
    const int bkh  = ((lane >> 3) & 1) * 8;
    const uint32_t aB = sb + 2 * (B_E + brow * PADK + bkh);

    const int arow = tid >> 3;
    const int amc  = (tid & 7) * 16;
    const __half* axh = g_xh + (size_t)arow * M_ + m0 + amc;
    const __half* axl = g_xl + (size_t)arow * M_ + m0 + amc;
    const int srow = tid >> 2;
    const int sv   = tid & 3;
    const uint4* pwf = reinterpret_cast<const uint4*>(g_wf + (size_t)(n0 + srow) * F_) + sv;

    float acc[4][2][4];
#pragma unroll
    for (int mt = 0; mt < 4; mt++)
#pragma unroll
        for (int nt = 0; nt < 2; nt++)
#pragma unroll
            for (int r = 0; r < 4; r++) acc[mt][nt][r] = 0.f;

    uint4 rah0 = *reinterpret_cast<const uint4*>(axh);
    uint4 rah1 = *reinterpret_cast<const uint4*>(axh + 8);
    uint4 ral0 = *reinterpret_cast<const uint4*>(axl);
    uint4 ral1 = *reinterpret_cast<const uint4*>(axl + 8);
    uint4 rb   = pwf[0];

    const int NKT = F_ / 32;
    for (int kt = 0; kt < NKT; kt++) {
        const int be = (kt & 1) * BUFE;
        __half* buf = sm + be;
        *reinterpret_cast<uint4*>(buf + AH_E + arow * PADM + amc)     = rah0;
        *reinterpret_cast<uint4*>(buf + AH_E + arow * PADM + amc + 8) = rah1;
        *reinterpret_cast<uint4*>(buf + AL_E + arow * PADM + amc)     = ral0;
        *reinterpret_cast<uint4*>(buf + AL_E + arow * PADM + amc + 8) = ral1;
        *reinterpret_cast<uint4*>(buf + B_E + srow * PADK + sv * 8)   = rb;
        __syncthreads();

        if (kt < NKT - 1) {
            const size_t ao = (size_t)(kt + 1) * 32 * M_;
            rah0 = *reinterpret_cast<const uint4*>(axh + ao);
            rah1 = *reinterpret_cast<const uint4*>(axh + ao + 8);
            ral0 = *reinterpret_cast<const uint4*>(axl + ao);
            ral1 = *reinterpret_cast<const uint4*>(axl + ao + 8);
            rb   = pwf[(kt + 1) * 4];
        }

        const uint32_t bofs = 2 * be;
#pragma unroll
        for (int ks = 0; ks < 32; ks += 16) {
            uint32_t bh[4];
            ldsm4(bh, aB + bofs + 2 * ks);
#pragma unroll
            for (int mt = 0; mt < 4; mt++) {
                const uint32_t ao = bofs + 2 * (ks * PADM + mt * 16);
                uint32_t ah[4], al[4];
                ldsm4t(ah, aAh + ao);
                ldsm4t(al, aAl + ao);
                mma_f16(acc[mt][0], ah, bh[0], bh[1]);
                mma_f16(acc[mt][1], ah, bh[2], bh[3]);
                mma_f16(acc[mt][0], al, bh[0], bh[1]);
                mma_f16(acc[mt][1], al, bh[2], bh[3]);
            }
        }
    }

#pragma unroll
    for (int nt = 0; nt < 2; nt++) {
        int n = n0 + wn + nt * 8 + 2 * tq;
        float2 bias = *reinterpret_cast<const float2*>(&bl[n]);
#pragma unroll
        for (int mt = 0; mt < 4; mt++) {
            int m = m0 + wm + mt * 16 + g;
            float2 o0, o1;
            o0.x = acc[mt][nt][0] + bias.x;  o0.y = acc[mt][nt][1] + bias.y;
            o1.x = acc[mt][nt][2] + bias.x;  o1.y = acc[mt][nt][3] + bias.y;
            *reinterpret_cast<float2*>(&g_G[(size_t)m * G4 + n])       = o0;
            *reinterpret_cast<float2*>(&g_G[(size_t)(m + 8) * G4 + n]) = o1;
        }
    }
}

// ---------------------------------------------------------------------------
// Kernel 2: LSTM recurrence. 1 CTA/batch, 512 threads = 16 warps.
// Lane pair (2j, 2j+1) of warp w owns column (gate = j>>2, unit = 4w+(j&3)),
// with K split between the two lanes (kh = lane&1): matvec chain is 4 deep,
// halves combine with one shfl.bfly. All 4 gates of a unit live in-warp, so
// the activated-gate gather stays 4 shfl.idx. One __syncthreads per step.
// ---------------------------------------------------------------------------
__device__ __forceinline__ unsigned long long pk2(float lo, float hi) {
    unsigned long long r;
    asm("mov.b64 %0, {%1, %2};" : "=l"(r) : "f"(lo), "f"(hi));
    return r;
}
__device__ __forceinline__ unsigned long long fma2_(unsigned long long a,
                                                    unsigned long long b,
                                                    unsigned long long c) {
    unsigned long long d;
    asm("fma.rn.f32x2 %0, %1, %2, %3;" : "=l"(d) : "l"(a), "l"(b), "l"(c));
    return d;
}
__device__ __forceinline__ unsigned long long add2_(unsigned long long a,
                                                    unsigned long long b) {
    unsigned long long d;
    asm("add.rn.f32x2 %0, %1, %2;" : "=l"(d) : "l"(a), "l"(b));
    return d;
}
__device__ __forceinline__ void upk2(float& lo, float& hi, unsigned long long v) {
    asm("mov.b64 {%0, %1}, %2;" : "=f"(lo), "=f"(hi) : "l"(v));
}
__device__ __forceinline__ float ex2_(float v) {
    float r; asm("ex2.approx.f32 %0, %1;" : "=f"(r) : "f"(v)); return r;
}
__device__ __forceinline__ float rcp_(float v) {
    float r; asm("rcp.approx.f32 %0, %1;" : "=f"(r) : "f"(v)); return r;
}

__global__ __launch_bounds__(512, 1)
void lstm_rec(const float* __restrict__ Wh, float* __restrict__ out) {
    const int b   = blockIdx.x;
    const int tid = threadIdx.x;
    const int w   = tid >> 5;          // warp 0..15
    const int l   = tid & 31;
    const int j   = l >> 1;            // column slot within warp, 0..15
    const int kh  = l & 1;             // K half: 0 -> k 0..31, 1 -> k 32..63
    const int uu  = j & 3;
    const int gq  = j >> 2;            // gate 0..3 (i,f,g,o)
    const int u   = 4 * w + uu;        // hidden unit 0..63
    const int n   = gq * 64 + u;       // column in [4H]

    __shared__ __align__(16) float Gsh[W_ * G4];     // 32 KB
    __shared__ __align__(16) float hbuf[2][H_];

    const float L2E = 1.4426950408889634f;
    const float fa2 = (gq == 2) ? -2.0f * L2E : -L2E;
    const float fb  = (gq == 2) ?  2.0f :  1.0f;
    const float fc  = (gq == 2) ? -1.0f :  0.0f;

    // this lane's half of Wh[:, n]: k = kh*32 .. kh*32+31 -> 16 f32x2
    unsigned long long wh2[16];
#pragma unroll
    for (int kk = 0; kk < 16; kk++)
        wh2[kk] = pk2(Wh[(kh * 32 + 2 * kk) * G4 + n],
                      Wh[(kh * 32 + 2 * kk + 1) * G4 + n]);

    {   // stage this batch's G slice into smem (coalesced, 4 float4/thread)
        const float4* src = reinterpret_cast<const float4*>(g_G + (size_t)b * W_ * G4);
        float4* dst = reinterpret_cast<float4*>(Gsh);
#pragma unroll
        for (int q = 0; q < 4; q++) dst[q * 512 + tid] = src[q * 512 + tid];
    }
    if (tid < H_) hbuf[0][tid] = 0.0f;
    float c = 0.0f;
    __syncthreads();

    int p = 0;
#pragma unroll 1
    for (int t = 0; t < W_; t++) {
        const unsigned long long* h2 =
            reinterpret_cast<const unsigned long long*>(hbuf[p]) + kh * 16;

        // G added once (kh==0 lane only; bfly sums the halves)
        unsigned long long a0 = pk2(kh == 0 ? Gsh[t * G4 + n] : 0.0f, 0.0f);
        unsigned long long a1 = 0ull, a2 = 0ull, a3 = 0ull;
#pragma unroll
        for (int kk = 0; kk < 4; kk++) {   // 16 fma2, 4 chains of 4
            a0 = fma2_(h2[kk],      wh2[kk],      a0);
            a1 = fma2_(h2[4 + kk],  wh2[4 + kk],  a1);
            a2 = fma2_(h2[8 + kk],  wh2[8 + kk],  a2);
            a3 = fma2_(h2[12 + kk], wh2[12 + kk], a3);
        }
        unsigned long long s = add2_(add2_(a0, a1), add2_(a2, a3));
        float slo, shi;
        upk2(slo, shi, s);
        float vh = slo + shi;
        // combine the two K halves
        float v = vh + __shfl_xor_sync(0xFFFFFFFFu, vh, 1);

        // own-gate activation (1 ex2 + 1 rcp), both kh lanes identical
        float act = fmaf(fb, rcp_(1.0f + ex2_(fa2 * v)), fc);

        // gather the 4 activated gates of unit u from lanes 2*(g*4+uu)
        float ig = __shfl_sync(0xFFFFFFFFu, act, 2 * uu);
        float fg = __shfl_sync(0xFFFFFFFFu, act, 8 + 2 * uu);
        float gg = __shfl_sync(0xFFFFFFFFu, act, 16 + 2 * uu);
        float og = __shfl_sync(0xFFFFFFFFu, act, 24 + 2 * uu);

        c = fg * c + ig * gg;
        float tc = fmaf(2.0f, rcp_(1.0f + ex2_(-2.0f * L2E * c)), -1.0f);  // tanh(c)
        float hn = og * tc;
        if (l < 8 && kh == 0) {            // lanes 0,2,4,6: j = uu, gate 0
            out[(size_t)b * (W_ * H_) + t * H_ + u] = c;   // output = cell state
            hbuf[p ^ 1][u] = hn;
        }
        p ^= 1;
        __syncthreads();
    }
}

// ---------------------------------------------------------------------------
// Launch
// ---------------------------------------------------------------------------
extern "C" void kernel_launch(void* const* d_in, const int* in_sizes, int n_in,
                              void* d_out, int out_size) {
    const float* x   = (const float*)d_in[0];   // [B, F, W]
    // d_in[1..5] (attention params) are dead: softmax over size-1 axis == 1.
    const float* Wx  = (const float*)d_in[6];   // [F, 4H]
    const float* Wh  = (const float*)d_in[7];   // [H, 4H]
    const float* blm = (const float*)d_in[8];   // [4H]
    float* out = (float*)d_out;                 // [B, W, H]

    cudaFuncSetAttribute(gate_gemm_mma,
                         cudaFuncAttributeMaxDynamicSharedMemorySize, GEMM_SMEM);

    split_xw<<<1088, 256>>>(x, Wx);
    gate_gemm_mma<<<dim3(32, 4), 256, GEMM_SMEM>>>(blm);
    lstm_rec<<<B_, 512>>>(Wh, out);
}

// round 16
// speedup vs baseline: 1.3097x; 1.3097x over previous
#include <cuda_runtime.h>
#include <cuda_fp16.h>
#include <cstdint>

// ---------------------------------------------------------------------------
// Problem: B=128, F=1024, W=32, H=64.  softmax over a size-1 axis == 1, so the
// attention branch is dead; model = plain LSTM, output = CELL state per step.
//   G[m][n] = sum_k x[b][k][t] * Wx[k][n] + b_lstm[n],  m = b*32 + t
// GEMM: single-pass fp16 mma.sync (A and B both RN fp16; measured B-only
// error was 2.8e-4, adding A-RN gives ~4e-4, 2.5x under the 1e-3 gate).
// x conversion stored [k][m]: NO transpose; A-fragments via ldmatrix.x4.trans.
// ---------------------------------------------------------------------------
#define B_   128
#define F_   1024
#define W_   32
#define H_   64
#define G4   256
#define M_   4096                // B_*W_
#define PADK 40                  // B smem row stride (fp16)
#define PADM 136                 // A smem row stride (fp16): 272B, ldsm-safe

__device__ float   g_G [M_ * G4];        // gate preactivations, 4 MB
__device__ __half  g_xf[F_ * M_];        // x fp16 RN [k][m], 8 MB
__device__ __half  g_wf[G4 * F_];        // Wx^T fp16 RN [n][k], 512 KB

// ---- helpers ---------------------------------------------------------------
__device__ __forceinline__ uint32_t smaddr(const void* p) {
    return (uint32_t)__cvta_generic_to_shared(p);
}
__device__ __forceinline__ uint32_t pack2h(float a, float b) {
    __half2 h = __floats2half2_rn(a, b);
    return *reinterpret_cast<uint32_t*>(&h);
}
__device__ __forceinline__ void mma_f16(float* c,
                                        const uint32_t* a, uint32_t b0, uint32_t b1) {
    asm volatile(
        "mma.sync.aligned.m16n8k16.row.col.f32.f16.f16.f32 "
        "{%0,%1,%2,%3}, {%4,%5,%6,%7}, {%8,%9}, {%0,%1,%2,%3};\n"
        : "+f"(c[0]), "+f"(c[1]), "+f"(c[2]), "+f"(c[3])
        : "r"(a[0]), "r"(a[1]), "r"(a[2]), "r"(a[3]), "r"(b0), "r"(b1));
}
__device__ __forceinline__ void ldsm4(uint32_t* r, uint32_t addr) {
    asm volatile("ldmatrix.sync.aligned.m8n8.x4.shared.b16 {%0,%1,%2,%3}, [%4];"
                 : "=r"(r[0]), "=r"(r[1]), "=r"(r[2]), "=r"(r[3]) : "r"(addr));
}
__device__ __forceinline__ void ldsm4t(uint32_t* r, uint32_t addr) {
    asm volatile("ldmatrix.sync.aligned.m8n8.x4.trans.shared.b16 {%0,%1,%2,%3}, [%4];"
                 : "=r"(r[0]), "=r"(r[1]), "=r"(r[2]), "=r"(r[3]) : "r"(addr));
}

// ---------------------------------------------------------------------------
// Kernel 0 (fused): fp16 RN conversion.
//   blocks [0, 512):   x [B][F][W] -> g_xf [k=f][m=b*32+t]  (no transpose;
//                      8 t per thread: 2x LDG.128 -> 1x STG.128)
//   blocks [512, 576): Wx [K][N]   -> g_wf [n][k]  (smem transpose)
// ---------------------------------------------------------------------------
__global__ __launch_bounds__(256) void split_xw(const float* __restrict__ x,
                                                const float* __restrict__ Wx) {
    const int tid = threadIdx.x;
    const int bid = blockIdx.x;

    if (bid < 512) {
        const int gtid = bid * 256 + tid;
#pragma unroll
        for (int j = 0; j < 4; j++) {
            int idx = j * 131072 + gtid;        // over (f, b, th): 1024*128*4
            int th  = idx & 3;                  // group of 8 t
            int rem = idx >> 2;
            int b   = rem & 127;
            int f   = rem >> 7;                 // 0..1023
            const float* src = x + ((size_t)b * F_ + f) * W_ + th * 8;
            float4 v0 = *reinterpret_cast<const float4*>(src);
            float4 v1 = *reinterpret_cast<const float4*>(src + 4);
            uint4 h;
            h.x = pack2h(v0.x, v0.y);
            h.y = pack2h(v0.z, v0.w);
            h.z = pack2h(v1.x, v1.y);
            h.w = pack2h(v1.z, v1.w);
            *reinterpret_cast<uint4*>(g_xf + (size_t)f * M_ + b * 32 + th * 8) = h;
        }
    } else {
        __shared__ float tile[64 * 65];
        const int id = bid - 512;
        const int k0 = (id & 15) * 64;
        const int n0 = (id >> 4) * 64;
#pragma unroll
        for (int i = 0; i < 4; i++) {
            int idx = i * 256 + tid;
            int k = idx >> 4, nq = idx & 15;
            float4 v = *reinterpret_cast<const float4*>(
                Wx + (size_t)(k0 + k) * G4 + n0 + nq * 4);
            tile[k * 65 + nq * 4 + 0] = v.x; tile[k * 65 + nq * 4 + 1] = v.y;
            tile[k * 65 + nq * 4 + 2] = v.z; tile[k * 65 + nq * 4 + 3] = v.w;
        }
        __syncthreads();
        const int n  = tid >> 2;
        const int ko = (tid & 3) * 16;
        uint32_t hi[8];
#pragma unroll
        for (int p = 0; p < 8; p++)
            hi[p] = pack2h(tile[(ko + 2 * p) * 65 + n], tile[(ko + 2 * p + 1) * 65 + n]);
        size_t dst = (size_t)(n0 + n) * F_ + k0 + ko;
        *reinterpret_cast<uint4*>(g_wf + dst)     = make_uint4(hi[0], hi[1], hi[2], hi[3]);
        *reinterpret_cast<uint4*>(g_wf + dst + 8) = make_uint4(hi[4], hi[5], hi[6], hi[7]);
    }
}

// ---------------------------------------------------------------------------
// Kernel 1: single-pass fp16 mma.sync GEMM.
// A tiles [k=32][m=128] (PADM), fragments via ldmatrix.x4.trans; B tiles
// [n=64][k=32] (PADK), non-trans. CTA tile 128x64, BK=32, grid (32,4),
// 256 threads = 8 warps (2m x 4n), warp tile m64 x n16. Double-buffered,
// one __syncthreads per k-tile.
// ---------------------------------------------------------------------------
#define A_E   0
#define B_E   (32 * PADM)                            // 4352
#define BUFE  (32 * PADM + 64 * PADK)                // 6912 elems = 13824 B
#define GEMM_SMEM (2 * BUFE * 2)                     // 27648 B

__global__ __launch_bounds__(256, 1)
void gate_gemm_mma(const float* __restrict__ bl) {
    extern __shared__ __half sm[];

    const int tid  = threadIdx.x;
    const int warp = tid >> 5;
    const int lane = tid & 31;
    const int wm   = (warp >> 2) * 64;      // 0 or 64
    const int wn   = (warp & 3) * 16;       // 0,16,32,48
    const int g    = lane >> 2;
    const int tq   = lane & 3;
    const int m0   = blockIdx.x * 128;
    const int n0   = blockIdx.y * 64;

    const uint32_t sb = smaddr(sm);
    // A trans-ldmatrix per-lane offsets (layout proven R11/R13)
    const int aoff = ((lane & 7) + ((lane >> 4) & 1) * 8) * PADM
                   + ((lane >> 3) & 1) * 8 + wm;
    const uint32_t aA = sb + 2 * (A_E + aoff);
    // B non-trans (layout proven R8)
    const int brow = wn + (lane & 7) + ((lane >> 4) & 1) * 8;
    const int bkh  = ((lane >> 3) & 1) * 8;
    const uint32_t aB = sb + 2 * (B_E + brow * PADK + bkh);

    // staging: A [32 k][128 m]: 8 threads/row, 2 uint4/thread
    const int arow = tid >> 3;              // 0..31
    const int amc  = (tid & 7) * 16;
    const __half* axf = g_xf + (size_t)arow * M_ + m0 + amc;
    //          B [64 n][32 k]: 4 threads/row, 1 uint4/thread
    const int srow = tid >> 2;              // 0..63
    const int sv   = tid & 3;
    const uint4* pwf = reinterpret_cast<const uint4*>(g_wf + (size_t)(n0 + srow) * F_) + sv;

    float acc[4][2][4];
#pragma unroll
    for (int mt = 0; mt < 4; mt++)
#pragma unroll
        for (int nt = 0; nt < 2; nt++)
#pragma unroll
            for (int r = 0; r < 4; r++) acc[mt][nt][r] = 0.f;

    uint4 ra0 = *reinterpret_cast<const uint4*>(axf);
    uint4 ra1 = *reinterpret_cast<const uint4*>(axf + 8);
    uint4 rb  = pwf[0];

    const int NKT = F_ / 32;
    for (int kt = 0; kt < NKT; kt++) {
        const int be = (kt & 1) * BUFE;
        __half* buf = sm + be;
        *reinterpret_cast<uint4*>(buf + A_E + arow * PADM + amc)     = ra0;
        *reinterpret_cast<uint4*>(buf + A_E + arow * PADM + amc + 8) = ra1;
        *reinterpret_cast<uint4*>(buf + B_E + srow * PADK + sv * 8)  = rb;
        __syncthreads();

        if (kt < NKT - 1) {                 // prefetch next k-tile
            const size_t ao = (size_t)(kt + 1) * 32 * M_;
            ra0 = *reinterpret_cast<const uint4*>(axf + ao);
            ra1 = *reinterpret_cast<const uint4*>(axf + ao + 8);
            rb  = pwf[(kt + 1) * 4];
        }

        const uint32_t bofs = 2 * be;
#pragma unroll
        for (int ks = 0; ks < 32; ks += 16) {
            uint32_t bh[4];
            ldsm4(bh, aB + bofs + 2 * ks);
#pragma unroll
            for (int mt = 0; mt < 4; mt++) {
                const uint32_t ao = bofs + 2 * (ks * PADM + mt * 16);
                uint32_t ah[4];
                ldsm4t(ah, aA + ao);
                mma_f16(acc[mt][0], ah, bh[0], bh[1]);
                mma_f16(acc[mt][1], ah, bh[2], bh[3]);
            }
        }
        // single barrier per iter is safe with double buffering (see R7 note)
    }

    // epilogue: bias + store (c0,c1 at row g, c2,c3 at g+8)
#pragma unroll
    for (int nt = 0; nt < 2; nt++) {
        int n = n0 + wn + nt * 8 + 2 * tq;
        float2 bias = *reinterpret_cast<const float2*>(&bl[n]);
#pragma unroll
        for (int mt = 0; mt < 4; mt++) {
            int m = m0 + wm + mt * 16 + g;
            float2 o0, o1;
            o0.x = acc[mt][nt][0] + bias.x;  o0.y = acc[mt][nt][1] + bias.y;
            o1.x = acc[mt][nt][2] + bias.x;  o1.y = acc[mt][nt][3] + bias.y;
            *reinterpret_cast<float2*>(&g_G[(size_t)m * G4 + n])       = o0;
            *reinterpret_cast<float2*>(&g_G[(size_t)(m + 8) * G4 + n]) = o1;
        }
    }
}

// ---------------------------------------------------------------------------
// Kernel 2: LSTM recurrence (R13/R11, proven 16.3us). 1 CTA/batch, 256 thr.
// Lane l of warp w: dot for (gate = l>>3, unit = 8w + (l&7)); G in smem;
// f32x2 matvec; own-gate MUFU activation then shuffle; one bar per step.
// ---------------------------------------------------------------------------
__device__ __forceinline__ unsigned long long pk2(float lo, float hi) {
    unsigned long long r;
    asm("mov.b64 %0, {%1, %2};" : "=l"(r) : "f"(lo), "f"(hi));
    return r;
}
__device__ __forceinline__ unsigned long long fma2_(unsigned long long a,
                                                    unsigned long long b,
                                                    unsigned long long c) {
    unsigned long long d;
    asm("fma.rn.f32x2 %0, %1, %2, %3;" : "=l"(d) : "l"(a), "l"(b), "l"(c));
    return d;
}
__device__ __forceinline__ void upk2(float& lo, float& hi, unsigned long long v) {
    asm("mov.b64 {%0, %1}, %2;" : "=f"(lo), "=f"(hi) : "l"(v));
}
__device__ __forceinline__ float ex2_(float v) {
    float r; asm("ex2.approx.f32 %0, %1;" : "=f"(r) : "f"(v)); return r;
}
__device__ __forceinline__ float rcp_(float v) {
    float r; asm("rcp.approx.f32 %0, %1;" : "=f"(r) : "f"(v)); return r;
}

__global__ __launch_bounds__(256, 1)
void lstm_rec(const float* __restrict__ Wh, float* __restrict__ out) {
    const int b   = blockIdx.x;
    const int tid = threadIdx.x;
    const int w   = tid >> 5;
    const int l   = tid & 31;
    const int u   = 8 * w + (l & 7);
    const int gq  = l >> 3;
    const int n   = gq * 64 + u;

    __shared__ __align__(16) float Gsh[W_ * G4];     // 32 KB
    __shared__ __align__(16) float hbuf[2][H_];

    const float L2E = 1.4426950408889634f;
    const float fa2 = (gq == 2) ? -2.0f * L2E : -L2E;
    const float fb  = (gq == 2) ?  2.0f :  1.0f;
    const float fc  = (gq == 2) ? -1.0f :  0.0f;

    unsigned long long wh2[32];
#pragma unroll
    for (int kk = 0; kk < 32; kk++)
        wh2[kk] = pk2(Wh[(2 * kk) * G4 + n], Wh[(2 * kk + 1) * G4 + n]);

    {   // stage this batch's G slice into smem (coalesced)
        const float4* src = reinterpret_cast<const float4*>(g_G + (size_t)b * W_ * G4);
        float4* dst = reinterpret_cast<float4*>(Gsh);
#pragma unroll
        for (int j = 0; j < 8; j++) dst[j * 256 + tid] = src[j * 256 + tid];
    }
    if (tid < H_) hbuf[0][tid] = 0.0f;
    float c = 0.0f;
    __syncthreads();

    int p = 0;
#pragma unroll 1
    for (int t = 0; t < W_; t++) {
        const unsigned long long* h2 =
            reinterpret_cast<const unsigned long long*>(hbuf[p]);

        unsigned long long a0 = pk2(Gsh[t * G4 + n], 0.0f);
        unsigned long long a1 = 0ull, a2 = 0ull, a3 = 0ull;
#pragma unroll
        for (int kk = 0; kk < 8; kk++) {
            a0 = fma2_(h2[kk],      wh2[kk],      a0);
            a1 = fma2_(h2[8 + kk],  wh2[8 + kk],  a1);
            a2 = fma2_(h2[16 + kk], wh2[16 + kk], a2);
            a3 = fma2_(h2[24 + kk], wh2[24 + kk], a3);
        }
        float s0, s1, s2, s3, s4, s5, s6, s7;
        upk2(s0, s1, a0); upk2(s2, s3, a1);
        upk2(s4, s5, a2); upk2(s6, s7, a3);
        float v = ((s0 + s1) + (s2 + s3)) + ((s4 + s5) + (s6 + s7));

        float act = fmaf(fb, rcp_(1.0f + ex2_(fa2 * v)), fc);

        int src = l & 7;
        float ig = __shfl_sync(0xFFFFFFFFu, act, src);
        float fg = __shfl_sync(0xFFFFFFFFu, act, src + 8);
        float gg = __shfl_sync(0xFFFFFFFFu, act, src + 16);
        float og = __shfl_sync(0xFFFFFFFFu, act, src + 24);

        c = fg * c + ig * gg;
        float tc = fmaf(2.0f, rcp_(1.0f + ex2_(-2.0f * L2E * c)), -1.0f);  // tanh(c)
        float hn = og * tc;
        if (l < 8) {
            out[(size_t)b * (W_ * H_) + t * H_ + u] = c;   // output = cell state
            hbuf[p ^ 1][u] = hn;
        }
        p ^= 1;
        __syncthreads();
    }
}

// ---------------------------------------------------------------------------
// Launch
// ---------------------------------------------------------------------------
extern "C" void kernel_launch(void* const* d_in, const int* in_sizes, int n_in,
                              void* d_out, int out_size) {
    const float* x   = (const float*)d_in[0];   // [B, F, W]
    // d_in[1..5] (attention params) are dead: softmax over size-1 axis == 1.
    const float* Wx  = (const float*)d_in[6];   // [F, 4H]
    const float* Wh  = (const float*)d_in[7];   // [H, 4H]
    const float* blm = (const float*)d_in[8];   // [4H]
    float* out = (float*)d_out;                 // [B, W, H]

    cudaFuncSetAttribute(gate_gemm_mma,
                         cudaFuncAttributeMaxDynamicSharedMemorySize, GEMM_SMEM);

    split_xw<<<576, 256>>>(x, Wx);
    gate_gemm_mma<<<dim3(32, 4), 256, GEMM_SMEM>>>(blm);
    lstm_rec<<<B_, 256>>>(Wh, out);
}